// round 2
// baseline (speedup 1.0000x reference)
#include <cuda_runtime.h>

#define WIDTH  512
#define HEIGHT 512
#define ROWS   32
#define TPB    128

#define W0f 0.30780133f
#define W1f 0.38439734f
#define C1f 1.0e-4f
#define C2f 9.0e-4f

#define NPART 4096   // >= (HEIGHT/ROWS) * planes = 16*96 = 1536

typedef unsigned long long u64;

__device__ float g_part[NPART];

// ---- f32x2 packed helpers (sm_103a FFMA2 path, PTX-only) ----
__device__ __forceinline__ u64 pk(float lo, float hi) {
    u64 r; asm("mov.b64 %0, {%1, %2};" : "=l"(r) : "f"(lo), "f"(hi)); return r;
}
__device__ __forceinline__ void upk(float& lo, float& hi, u64 p) {
    asm("mov.b64 {%0, %1}, %2;" : "=f"(lo), "=f"(hi) : "l"(p));
}
__device__ __forceinline__ u64 mul2(u64 a, u64 b) {
    u64 r; asm("mul.rn.f32x2 %0, %1, %2;" : "=l"(r) : "l"(a), "l"(b)); return r;
}
__device__ __forceinline__ u64 add2(u64 a, u64 b) {
    u64 r; asm("add.rn.f32x2 %0, %1, %2;" : "=l"(r) : "l"(a), "l"(b)); return r;
}
__device__ __forceinline__ u64 fma2(u64 a, u64 b, u64 c) {
    u64 r; asm("fma.rn.f32x2 %0, %1, %2, %3;" : "=l"(r) : "l"(a), "l"(b), "l"(c)); return r;
}
__device__ __forceinline__ u64 cpk(float c) {
    unsigned u = __float_as_uint(c); return ((u64)u << 32) | u;
}
// 3-tap horizontal: W0*(l+r) + W1*c, packed
__device__ __forceinline__ u64 hs2(u64 l, u64 c, u64 r, u64 W0p, u64 W1p) {
    return fma2(add2(l, r), W0p, mul2(c, W1p));
}

__global__ void __launch_bounds__(TPB, 4)
k_ssim(const float* __restrict__ A, const float* __restrict__ B) {
    const int plane = blockIdx.y;
    const int y0    = blockIdx.x * ROWS;
    const float* a = A + plane * (WIDTH * HEIGHT);
    const float* b = B + plane * (WIDTH * HEIGHT);

    const int t    = threadIdx.x;
    const int lane = t & 31;
    const int x0   = t << 2;

    const u64 W0p = cpk(W0f), W1p = cpk(W1f);
    const u64 C1p = cpk(C1f), C2p = cpk(C2f);
    const u64 TWOp = cpk(2.0f), NEGp = cpk(-1.0f);

    // streaming vertical partials: [quantity(5) x pair(2)]
    u64 P1[10], P2[10];
#pragma unroll
    for (int i = 0; i < 10; ++i) { P1[i] = 0ull; P2[i] = 0ull; }

    float acc0 = 0.f, acc1 = 0.f;

#pragma unroll 1
    for (int it = 0; it < ROWS + 2; ++it) {
        const int r = y0 - 1 + it;
        const bool rv = (r >= 0) && (r < HEIGHT);

        float4 av, bv;
        if (rv) {
            av = *reinterpret_cast<const float4*>(a + r * WIDTH + x0);
            bv = *reinterpret_cast<const float4*>(b + r * WIDTH + x0);
        } else {
            av = make_float4(0.f, 0.f, 0.f, 0.f);
            bv = make_float4(0.f, 0.f, 0.f, 0.f);
        }

        float la = __shfl_up_sync(0xffffffffu, av.w, 1);
        float ra = __shfl_down_sync(0xffffffffu, av.x, 1);
        float lb = __shfl_up_sync(0xffffffffu, bv.w, 1);
        float rb = __shfl_down_sync(0xffffffffu, bv.x, 1);
        if (lane == 0) {
            la = (rv && x0 > 0) ? a[r * WIDTH + x0 - 1] : 0.f;
            lb = (rv && x0 > 0) ? b[r * WIDTH + x0 - 1] : 0.f;
        }
        if (lane == 31) {
            ra = (rv && x0 + 4 < WIDTH) ? a[r * WIDTH + x0 + 4] : 0.f;
            rb = (rv && x0 + 4 < WIDTH) ? b[r * WIDTH + x0 + 4] : 0.f;
        }

        // shifted raw packs: index i holds (v_i, v_{i+1})
        u64 Ap[5], Bp[5];
        Ap[0] = pk(la, av.x);   Ap[1] = pk(av.x, av.y); Ap[2] = pk(av.y, av.z);
        Ap[3] = pk(av.z, av.w); Ap[4] = pk(av.w, ra);
        Bp[0] = pk(lb, bv.x);   Bp[1] = pk(bv.x, bv.y); Bp[2] = pk(bv.y, bv.z);
        Bp[3] = pk(bv.z, bv.w); Bp[4] = pk(bv.w, rb);

        // products at even positions, shifted packs rebuilt via ALU movs
        u64 AA0 = mul2(Ap[0], Ap[0]), AA2 = mul2(Ap[2], Ap[2]), AA4 = mul2(Ap[4], Ap[4]);
        u64 BB0 = mul2(Bp[0], Bp[0]), BB2 = mul2(Bp[2], Bp[2]), BB4 = mul2(Bp[4], Bp[4]);
        u64 AB0 = mul2(Ap[0], Bp[0]), AB2 = mul2(Ap[2], Bp[2]), AB4 = mul2(Ap[4], Bp[4]);

        float aa0, aa1, aa2, aa3, aa4, aa5;
        upk(aa0, aa1, AA0); upk(aa2, aa3, AA2); upk(aa4, aa5, AA4);
        u64 AA1 = pk(aa1, aa2), AA3 = pk(aa3, aa4);
        float bb0, bb1, bb2, bb3, bb4, bb5;
        upk(bb0, bb1, BB0); upk(bb2, bb3, BB2); upk(bb4, bb5, BB4);
        u64 BB1 = pk(bb1, bb2), BB3 = pk(bb3, bb4);
        float ab0, ab1, ab2, ab3, ab4, ab5;
        upk(ab0, ab1, AB0); upk(ab2, ab3, AB2); upk(ab4, ab5, AB4);
        u64 AB1 = pk(ab1, ab2), AB3 = pk(ab3, ab4);

        // horizontal 3-tap sums; H[q*2+p]: pair p of quantity q
        u64 H[10];
        H[0] = hs2(Ap[0], Ap[1], Ap[2], W0p, W1p);
        H[1] = hs2(Ap[2], Ap[3], Ap[4], W0p, W1p);
        H[2] = hs2(Bp[0], Bp[1], Bp[2], W0p, W1p);
        H[3] = hs2(Bp[2], Bp[3], Bp[4], W0p, W1p);
        H[4] = hs2(AA0, AA1, AA2, W0p, W1p);
        H[5] = hs2(AA2, AA3, AA4, W0p, W1p);
        H[6] = hs2(BB0, BB1, BB2, W0p, W1p);
        H[7] = hs2(BB2, BB3, BB4, W0p, W1p);
        H[8] = hs2(AB0, AB1, AB2, W0p, W1p);
        H[9] = hs2(AB2, AB3, AB4, W0p, W1p);

        if (it >= 2) {
#pragma unroll
            for (int p = 0; p < 2; ++p) {
                u64 mu1 = fma2(H[0 + p], W0p, P1[0 + p]);
                u64 mu2 = fma2(H[2 + p], W0p, P1[2 + p]);
                u64 s11 = fma2(H[4 + p], W0p, P1[4 + p]);
                u64 s22 = fma2(H[6 + p], W0p, P1[6 + p]);
                u64 s12 = fma2(H[8 + p], W0p, P1[8 + p]);

                u64 m11 = mul2(mu1, mu1);
                u64 m22 = mul2(mu2, mu2);
                u64 m12 = mul2(mu1, mu2);

                u64 n1 = fma2(TWOp, m12, C1p);
                u64 sd = fma2(m12, NEGp, s12);
                u64 n2 = fma2(TWOp, sd, C2p);
                u64 d1 = add2(add2(m11, m22), C1p);
                u64 e1 = fma2(m11, NEGp, s11);
                u64 e2 = fma2(m22, NEGp, s22);
                u64 d2 = add2(add2(e1, e2), C2p);

                u64 num = mul2(n1, n2);
                u64 den = mul2(d1, d2);
                float nlo, nhi, dlo, dhi;
                upk(nlo, nhi, num); upk(dlo, dhi, den);
                acc0 += __fdividef(nlo, dlo);
                acc1 += __fdividef(nhi, dhi);
            }
        }
#pragma unroll
        for (int i = 0; i < 10; ++i) {
            P1[i] = fma2(H[i], W1p, P2[i]);
            P2[i] = mul2(H[i], W0p);
        }
    }

    // block reduction -> per-block partial
    __shared__ float red[TPB];
    red[t] = acc0 + acc1;
    __syncthreads();
#pragma unroll
    for (int s = TPB / 2; s > 0; s >>= 1) {
        if (t < s) red[t] += red[t + s];
        __syncthreads();
    }
    if (t == 0) g_part[blockIdx.y * gridDim.x + blockIdx.x] = red[0];
}

__global__ void __launch_bounds__(512)
k_fin(float* out, int nblocks) {
    __shared__ double red[512];
    const int t = threadIdx.x;
    double s = 0.0;
    for (int i = t; i < nblocks; i += 512) s += (double)g_part[i];
    red[t] = s;
    __syncthreads();
#pragma unroll
    for (int k = 256; k > 0; k >>= 1) {
        if (t < k) red[t] += red[t + k];
        __syncthreads();
    }
    if (t == 0) out[0] = (float)(1.0 - red[0]);
}

extern "C" void kernel_launch(void* const* d_in, const int* in_sizes, int n_in,
                              void* d_out, int out_size) {
    const float* A = (const float*)d_in[0];
    const float* B = (const float*)d_in[1];
    float* out = (float*)d_out;

    const int planes = in_sizes[0] / (WIDTH * HEIGHT);   // 96
    dim3 grid(HEIGHT / ROWS, planes);
    k_ssim<<<grid, TPB>>>(A, B);
    k_fin<<<1, 512>>>(out, grid.x * planes);
}

// round 3
// speedup vs baseline: 1.1124x; 1.1124x over previous
#include <cuda_runtime.h>

#define WIDTH  512
#define HEIGHT 512
#define ROWS   32
#define TPB    128
#define NPART  2048   // >= 16*96 blocks

// fp32 Gaussian taps (match reference normalization)
#define W0d 0.30780133
#define W1d 0.38439734
#define C1f 1.0e-4f
#define C2f 9.0e-4f

__device__ float g_part[NPART];

// unnormalized-tap constants; per-dim scale W0 folded into emit
__constant__ float cWC = (float)(W1d / W0d);                         // w
__constant__ float cA1 = (float)( 2.0 * W0d * W0d * W0d * W0d);      // 2k^2
__constant__ float cA2 = (float)( 2.0 * W0d * W0d);                  // 2k
__constant__ float cA3 = (float)(-2.0 * W0d * W0d * W0d * W0d);      // -2k^2
__constant__ float cA4 = (float)( W0d * W0d * W0d * W0d);            // k^2
__constant__ float cA5 = (float)( W0d * W0d);                        // k
__constant__ float cA6 = (float)(-(W0d * W0d * W0d * W0d));          // -k^2

// Load one input row pair and produce the 5 unnormalized horizontal 3-tap sums
// H[q*4+i], q in {a, b, aa, bb, ab}, for this thread's 4 pixels.
__device__ __forceinline__ void row_h(const float* __restrict__ a,
                                      const float* __restrict__ b,
                                      int r, int x0, int lane, float wc,
                                      float* __restrict__ H) {
    float4 av = *reinterpret_cast<const float4*>(a + r * WIDTH + x0);
    float4 bv = *reinterpret_cast<const float4*>(b + r * WIDTH + x0);

    float la = __shfl_up_sync(0xffffffffu, av.w, 1);
    float ra = __shfl_down_sync(0xffffffffu, av.x, 1);
    float lb = __shfl_up_sync(0xffffffffu, bv.w, 1);
    float rb = __shfl_down_sync(0xffffffffu, bv.x, 1);
    if (lane == 0) {
        la = (x0 > 0) ? a[r * WIDTH + x0 - 1] : 0.f;
        lb = (x0 > 0) ? b[r * WIDTH + x0 - 1] : 0.f;
    }
    if (lane == 31) {
        ra = (x0 + 4 < WIDTH) ? a[r * WIDTH + x0 + 4] : 0.f;
        rb = (x0 + 4 < WIDTH) ? b[r * WIDTH + x0 + 4] : 0.f;
    }

    float va[6] = { la, av.x, av.y, av.z, av.w, ra };
    float vb[6] = { lb, bv.x, bv.y, bv.z, bv.w, rb };
    float paa[6], pbb[6], pab[6];
#pragma unroll
    for (int j = 0; j < 6; ++j) {
        paa[j] = va[j] * va[j];
        pbb[j] = vb[j] * vb[j];
        pab[j] = va[j] * vb[j];
    }
#pragma unroll
    for (int i = 0; i < 4; ++i) {
        H[ 0 + i] = fmaf(wc, va[i + 1],  va[i]  + va[i + 2]);
        H[ 4 + i] = fmaf(wc, vb[i + 1],  vb[i]  + vb[i + 2]);
        H[ 8 + i] = fmaf(wc, paa[i + 1], paa[i] + paa[i + 2]);
        H[12 + i] = fmaf(wc, pbb[i + 1], pbb[i] + pbb[i + 2]);
        H[16 + i] = fmaf(wc, pab[i + 1], pab[i] + pab[i + 2]);
    }
}

// Vertical 3-tap + SSIM emit for 4 pixels, given Hm1/Hc/Hn (rows r-1, r, r+1).
__device__ __forceinline__ void emit4(const float* __restrict__ Hm1,
                                      const float* __restrict__ Hc,
                                      const float* __restrict__ Hn,
                                      float wc, float A1, float A2, float A3,
                                      float A4, float A5, float A6,
                                      float& acc) {
#pragma unroll
    for (int i = 0; i < 4; ++i) {
        float U1  = fmaf(wc, Hc[ 0 + i], Hm1[ 0 + i] + Hn[ 0 + i]);
        float U2  = fmaf(wc, Hc[ 4 + i], Hm1[ 4 + i] + Hn[ 4 + i]);
        float S11 = fmaf(wc, Hc[ 8 + i], Hm1[ 8 + i] + Hn[ 8 + i]);
        float S22 = fmaf(wc, Hc[12 + i], Hm1[12 + i] + Hn[12 + i]);
        float S12 = fmaf(wc, Hc[16 + i], Hm1[16 + i] + Hn[16 + i]);

        float m11 = U1 * U1;
        float m22 = U2 * U2;
        float m12 = U1 * U2;
        float msum = m11 + m22;
        float ssum = S11 + S22;

        float n1 = fmaf(A1, m12, C1f);
        float n2 = fmaf(A2, S12, fmaf(A3, m12, C2f));
        float d1 = fmaf(A4, msum, C1f);
        float d2 = fmaf(A5, ssum, fmaf(A6, msum, C2f));

        acc += __fdividef(n1 * n2, d1 * d2);
    }
}

__global__ void __launch_bounds__(TPB)
k_ssim(const float* __restrict__ A, const float* __restrict__ B) {
    const int plane = blockIdx.y;
    const int y0    = blockIdx.x * ROWS;
    const float* a = A + plane * (WIDTH * HEIGHT);
    const float* b = B + plane * (WIDTH * HEIGHT);

    const int t    = threadIdx.x;
    const int lane = t & 31;
    const int x0   = t << 2;

    const float wc = cWC;
    const float A1 = cA1, A2 = cA2, A3 = cA3, A4 = cA4, A5 = cA5, A6 = cA6;

    float Hm1[20], Hc[20], Hn[20];
    float acc = 0.f;

    // prologue: H for rows y0-1 (zero-pad at top) and y0
    if (y0 > 0) {
        row_h(a, b, y0 - 1, x0, lane, wc, Hm1);
    } else {
#pragma unroll
        for (int i = 0; i < 20; ++i) Hm1[i] = 0.f;
    }
    row_h(a, b, y0, x0, lane, wc, Hc);

    // main: rows y0+1 .. y0+31 always in-bounds
#pragma unroll 4
    for (int it = 0; it < ROWS - 1; ++it) {
        row_h(a, b, y0 + 1 + it, x0, lane, wc, Hn);
        emit4(Hm1, Hc, Hn, wc, A1, A2, A3, A4, A5, A6, acc);
#pragma unroll
        for (int i = 0; i < 20; ++i) { Hm1[i] = Hc[i]; Hc[i] = Hn[i]; }
    }

    // epilogue: row y0+32 (zero-pad at bottom for last strip)
    if (y0 + ROWS < HEIGHT) {
        row_h(a, b, y0 + ROWS, x0, lane, wc, Hn);
    } else {
#pragma unroll
        for (int i = 0; i < 20; ++i) Hn[i] = 0.f;
    }
    emit4(Hm1, Hc, Hn, wc, A1, A2, A3, A4, A5, A6, acc);

    // block reduction -> partial
    __shared__ float red[TPB];
    red[t] = acc;
    __syncthreads();
#pragma unroll
    for (int s = TPB / 2; s > 0; s >>= 1) {
        if (t < s) red[t] += red[t + s];
        __syncthreads();
    }
    if (t == 0) g_part[blockIdx.y * gridDim.x + blockIdx.x] = red[0];
}

__global__ void __launch_bounds__(512)
k_fin(float* out, int nblocks) {
    __shared__ double red[512];
    const int t = threadIdx.x;
    double s = 0.0;
    for (int i = t; i < nblocks; i += 512) s += (double)g_part[i];
    red[t] = s;
    __syncthreads();
#pragma unroll
    for (int k = 256; k > 0; k >>= 1) {
        if (t < k) red[t] += red[t + k];
        __syncthreads();
    }
    if (t == 0) out[0] = (float)(1.0 - red[0]);
}

extern "C" void kernel_launch(void* const* d_in, const int* in_sizes, int n_in,
                              void* d_out, int out_size) {
    const float* A = (const float*)d_in[0];
    const float* B = (const float*)d_in[1];
    float* out = (float*)d_out;

    const int planes = in_sizes[0] / (WIDTH * HEIGHT);   // 96
    dim3 grid(HEIGHT / ROWS, planes);
    k_ssim<<<grid, TPB>>>(A, B);
    k_fin<<<1, 512>>>(out, grid.x * planes);
}

// round 4
// speedup vs baseline: 1.3318x; 1.1973x over previous
#include <cuda_runtime.h>

#define WIDTH  512
#define HEIGHT 512
#define ROWS   64
#define TPB    128

#define W0d 0.30780133
#define W1d 0.38439734
#define C1f 1.0e-4f
#define C2f 9.0e-4f

__device__ double       g_acc   = 0.0;
__device__ unsigned int g_count = 0u;

// unnormalized-tap constants; per-dim scale W0 folded into emit constants
__constant__ float cWC = (float)(W1d / W0d);                      // w
__constant__ float cA1 = (float)( 2.0 * W0d * W0d * W0d * W0d);   // 2k^2
__constant__ float cA2 = (float)( 2.0 * W0d * W0d);               // 2k
__constant__ float cA3 = (float)(-2.0 * W0d * W0d * W0d * W0d);   // -2k^2
__constant__ float cA4 = (float)( W0d * W0d * W0d * W0d);         // k^2
__constant__ float cA5 = (float)( W0d * W0d);                     // k
__constant__ float cA6 = (float)(-(W0d * W0d * W0d * W0d));       // -k^2

__device__ __forceinline__ float frcp(float x) {
    float r; asm("rcp.approx.f32 %0, %1;" : "=f"(r) : "f"(x)); return r;
}

// One input row -> 5 unnormalized horizontal 3-tap sums H[q*4+i]
// (q in {a, b, aa, bb, ab}) for this thread's 4 pixels.
__device__ __forceinline__ void row_h(const float* __restrict__ a,
                                      const float* __restrict__ b,
                                      int r, int x0, int lane, float wc,
                                      float* __restrict__ H) {
    float4 av = *reinterpret_cast<const float4*>(a + r * WIDTH + x0);
    float4 bv = *reinterpret_cast<const float4*>(b + r * WIDTH + x0);

    float la = __shfl_up_sync(0xffffffffu, av.w, 1);
    float ra = __shfl_down_sync(0xffffffffu, av.x, 1);
    float lb = __shfl_up_sync(0xffffffffu, bv.w, 1);
    float rb = __shfl_down_sync(0xffffffffu, bv.x, 1);
    if (lane == 0) {
        la = (x0 > 0) ? a[r * WIDTH + x0 - 1] : 0.f;
        lb = (x0 > 0) ? b[r * WIDTH + x0 - 1] : 0.f;
    }
    if (lane == 31) {
        ra = (x0 + 4 < WIDTH) ? a[r * WIDTH + x0 + 4] : 0.f;
        rb = (x0 + 4 < WIDTH) ? b[r * WIDTH + x0 + 4] : 0.f;
    }

    float va[6] = { la, av.x, av.y, av.z, av.w, ra };
    float vb[6] = { lb, bv.x, bv.y, bv.z, bv.w, rb };
    float paa[6], pbb[6], pab[6];
#pragma unroll
    for (int j = 0; j < 6; ++j) {
        paa[j] = va[j] * va[j];
        pbb[j] = vb[j] * vb[j];
        pab[j] = va[j] * vb[j];
    }
#pragma unroll
    for (int i = 0; i < 4; ++i) {
        H[ 0 + i] = fmaf(wc, va[i + 1],  va[i]  + va[i + 2]);
        H[ 4 + i] = fmaf(wc, vb[i + 1],  vb[i]  + vb[i + 2]);
        H[ 8 + i] = fmaf(wc, paa[i + 1], paa[i] + paa[i + 2]);
        H[12 + i] = fmaf(wc, pbb[i + 1], pbb[i] + pbb[i + 2]);
        H[16 + i] = fmaf(wc, pab[i + 1], pab[i] + pab[i + 2]);
    }
}

// Emit output row using V = P1 + H (unnormalized separable conv result).
__device__ __forceinline__ void emit4(const float* __restrict__ P1,
                                      const float* __restrict__ H,
                                      float A1, float A2, float A3,
                                      float A4, float A5, float A6,
                                      float& acc) {
#pragma unroll
    for (int i = 0; i < 4; ++i) {
        float U1  = P1[ 0 + i] + H[ 0 + i];
        float U2  = P1[ 4 + i] + H[ 4 + i];
        float S11 = P1[ 8 + i] + H[ 8 + i];
        float S22 = P1[12 + i] + H[12 + i];
        float S12 = P1[16 + i] + H[16 + i];

        float m11 = U1 * U1;
        float m22 = U2 * U2;
        float m12 = U1 * U2;
        float msum = m11 + m22;
        float ssum = S11 + S22;

        float n1 = fmaf(A1, m12, C1f);
        float n2 = fmaf(A2, S12, fmaf(A3, m12, C2f));
        float d1 = fmaf(A4, msum, C1f);
        float d2 = fmaf(A5, ssum, fmaf(A6, msum, C2f));

        acc = fmaf(n1 * n2, frcp(d1 * d2), acc);
    }
}

__device__ __forceinline__ void update(float* __restrict__ P1,
                                       float* __restrict__ P2,
                                       const float* __restrict__ H, float wc) {
#pragma unroll
    for (int i = 0; i < 20; ++i) {
        P1[i] = fmaf(wc, H[i], P2[i]);
        P2[i] = H[i];
    }
}

__global__ void __launch_bounds__(TPB)
k_ssim(const float* __restrict__ A, const float* __restrict__ B,
       float* __restrict__ out, int nblocks) {
    const int plane = blockIdx.y;
    const int y0    = blockIdx.x * ROWS;
    const float* a = A + plane * (WIDTH * HEIGHT);
    const float* b = B + plane * (WIDTH * HEIGHT);

    const int t    = threadIdx.x;
    const int lane = t & 31;
    const int x0   = t << 2;

    const float wc = cWC;
    const float A1 = cA1, A2 = cA2, A3 = cA3, A4 = cA4, A5 = cA5, A6 = cA6;

    float P1[20], P2[20], H[20];
    float acc = 0.f;

    // r = y0-1 (zero row above the image for the top strip); no emit
    if (y0 > 0) {
        row_h(a, b, y0 - 1, x0, lane, wc, H);
#pragma unroll
        for (int i = 0; i < 20; ++i) { P1[i] = wc * H[i]; P2[i] = H[i]; }
    } else {
#pragma unroll
        for (int i = 0; i < 20; ++i) { P1[i] = 0.f; P2[i] = 0.f; }
    }

    // r = y0; no emit (its output row y0-1 belongs to the strip above)
    row_h(a, b, y0, x0, lane, wc, H);
    update(P1, P2, H, wc);

    // r = y0+1 .. y0+ROWS-1: always in-bounds; emit output rows y0..y0+ROWS-2
#pragma unroll 1
    for (int r = y0 + 1; r < y0 + ROWS; ++r) {
        row_h(a, b, r, x0, lane, wc, H);
        emit4(P1, H, A1, A2, A3, A4, A5, A6, acc);
        update(P1, P2, H, wc);
    }

    // r = y0+ROWS (zero row below for the bottom strip); emit last output row
    if (y0 + ROWS < HEIGHT) {
        row_h(a, b, y0 + ROWS, x0, lane, wc, H);
    } else {
#pragma unroll
        for (int i = 0; i < 20; ++i) H[i] = 0.f;
    }
    emit4(P1, H, A1, A2, A3, A4, A5, A6, acc);

    // block reduction
    __shared__ float red[TPB];
    red[t] = acc;
    __syncthreads();
#pragma unroll
    for (int s = TPB / 2; s > 0; s >>= 1) {
        if (t < s) red[t] += red[t + s];
        __syncthreads();
    }

    // global reduction: last arriving block finalizes and resets state
    if (t == 0) {
        atomicAdd(&g_acc, (double)red[0]);
        __threadfence();
        unsigned prev = atomicAdd(&g_count, 1u);
        if (prev == (unsigned)(nblocks - 1)) {
            double s = atomicAdd(&g_acc, 0.0);   // fresh serialized read
            out[0] = (float)(1.0 - s);
            g_acc   = 0.0;                        // reset for next graph replay
            __threadfence();
            g_count = 0u;
        }
    }
}

extern "C" void kernel_launch(void* const* d_in, const int* in_sizes, int n_in,
                              void* d_out, int out_size) {
    const float* A = (const float*)d_in[0];
    const float* B = (const float*)d_in[1];
    float* out = (float*)d_out;

    const int planes = in_sizes[0] / (WIDTH * HEIGHT);   // 96
    dim3 grid(HEIGHT / ROWS, planes);                    // 8 x 96 = 768 blocks
    k_ssim<<<grid, TPB>>>(A, B, out, grid.x * planes);
}